// round 4
// baseline (speedup 1.0000x reference)
#include <cuda_runtime.h>

// ---------------------------------------------------------------------------
// CrossVariateAdapter: B=16, C=1024, NP=512, DM=512, H=8, D=64, TOPK=16
// Outputs concatenated: M_tilde (16*1024*512 fp32) then A (16*1024*1024 fp32)
// ---------------------------------------------------------------------------

// Scratch (static device memory — allocation-free per harness rules)
static __device__ float g_Q[8388608];      // (B*H, C, D)  33.5 MB
static __device__ float g_K[8388608];
static __device__ float g_V[8388608];
static __device__ float g_S[134217728];    // (B*H, C, C)  512 MB
static __device__ float g_O[8388608];      // (B*C, DM)    33.5 MB

// ---------------------------------------------------------------------------
// Kernel 1: QKV projections.  q[m,n] = sum_k M[m,k] * W[n,k]
// Output laid out as (b, h, i, d) for the attention stage.
// BM=BN=64, BK=16, 256 threads, 4x4 micro-tile.
// ---------------------------------------------------------------------------
__global__ void __launch_bounds__(256) qkv_kernel(
    const float* __restrict__ Mm, const float* __restrict__ Wq,
    const float* __restrict__ Wk, const float* __restrict__ Wv)
{
    __shared__ float As[16][68];
    __shared__ float Bs[16][68];

    const float* W;
    float* out;
    if (blockIdx.z == 0)      { W = Wq; out = g_Q; }
    else if (blockIdx.z == 1) { W = Wk; out = g_K; }
    else                      { W = Wv; out = g_V; }

    int t  = threadIdx.x;
    int m0 = blockIdx.x << 6;     // over 16384
    int n0 = blockIdx.y << 6;     // over 512
    int tx = t & 15, ty = t >> 4;
    int lr = t >> 2, lk = (t & 3) << 2;

    float acc[4][4];
#pragma unroll
    for (int u = 0; u < 4; u++)
#pragma unroll
        for (int v = 0; v < 4; v++) acc[u][v] = 0.f;

    const float* Ap = Mm + (size_t)(m0 + lr) * 512 + lk;
    const float* Bp = W  + (size_t)(n0 + lr) * 512 + lk;

    for (int k0 = 0; k0 < 512; k0 += 16) {
        float4 av = *(const float4*)(Ap + k0);
        float4 bv = *(const float4*)(Bp + k0);
        As[lk + 0][lr] = av.x; As[lk + 1][lr] = av.y;
        As[lk + 2][lr] = av.z; As[lk + 3][lr] = av.w;
        Bs[lk + 0][lr] = bv.x; Bs[lk + 1][lr] = bv.y;
        Bs[lk + 2][lr] = bv.z; Bs[lk + 3][lr] = bv.w;
        __syncthreads();
#pragma unroll
        for (int k = 0; k < 16; k++) {
            float4 a = *(const float4*)&As[k][ty << 2];
            float4 b = *(const float4*)&Bs[k][tx << 2];
            float a4[4] = {a.x, a.y, a.z, a.w};
            float b4[4] = {b.x, b.y, b.z, b.w};
#pragma unroll
            for (int u = 0; u < 4; u++)
#pragma unroll
                for (int v = 0; v < 4; v++) acc[u][v] += a4[u] * b4[v];
        }
        __syncthreads();
    }

    int n  = n0 + (tx << 2);
    int hh = n >> 6, dd = n & 63;
#pragma unroll
    for (int u = 0; u < 4; u++) {
        int m  = m0 + (ty << 2) + u;
        int bb = m >> 10, ii = m & 1023;
        float4 r = make_float4(acc[u][0], acc[u][1], acc[u][2], acc[u][3]);
        *(float4*)&out[(((size_t)(bb * 8 + hh) << 10) + ii) * 64 + dd] = r;
    }
}

// ---------------------------------------------------------------------------
// Kernel 2: batched scores S[z] = (Q[z] @ K[z]^T) * D^-0.5, z = b*H + h
// M=N=1024, K=64.
// ---------------------------------------------------------------------------
__global__ void __launch_bounds__(256) scores_kernel()
{
    __shared__ float As[16][68];
    __shared__ float Bs[16][68];

    int z = blockIdx.z;                       // 0..127
    const float* Q = g_Q + ((size_t)z << 16); // *1024*64
    const float* K = g_K + ((size_t)z << 16);
    float*       S = g_S + ((size_t)z << 20); // *1024*1024

    int t  = threadIdx.x;
    int m0 = blockIdx.x << 6;
    int n0 = blockIdx.y << 6;
    int tx = t & 15, ty = t >> 4;
    int lr = t >> 2, lk = (t & 3) << 2;

    float acc[4][4];
#pragma unroll
    for (int u = 0; u < 4; u++)
#pragma unroll
        for (int v = 0; v < 4; v++) acc[u][v] = 0.f;

    const float* Ap = Q + (size_t)(m0 + lr) * 64 + lk;
    const float* Bp = K + (size_t)(n0 + lr) * 64 + lk;

    for (int k0 = 0; k0 < 64; k0 += 16) {
        float4 av = *(const float4*)(Ap + k0);
        float4 bv = *(const float4*)(Bp + k0);
        As[lk + 0][lr] = av.x; As[lk + 1][lr] = av.y;
        As[lk + 2][lr] = av.z; As[lk + 3][lr] = av.w;
        Bs[lk + 0][lr] = bv.x; Bs[lk + 1][lr] = bv.y;
        Bs[lk + 2][lr] = bv.z; Bs[lk + 3][lr] = bv.w;
        __syncthreads();
#pragma unroll
        for (int k = 0; k < 16; k++) {
            float4 a = *(const float4*)&As[k][ty << 2];
            float4 b = *(const float4*)&Bs[k][tx << 2];
            float a4[4] = {a.x, a.y, a.z, a.w};
            float b4[4] = {b.x, b.y, b.z, b.w};
#pragma unroll
            for (int u = 0; u < 4; u++)
#pragma unroll
                for (int v = 0; v < 4; v++) acc[u][v] += a4[u] * b4[v];
        }
        __syncthreads();
    }

    const float scale = 0.125f;   // 64^-0.5
#pragma unroll
    for (int u = 0; u < 4; u++) {
        int m = m0 + (ty << 2) + u;
        float4 r = make_float4(acc[u][0] * scale, acc[u][1] * scale,
                               acc[u][2] * scale, acc[u][3] * scale);
        *(float4*)&S[(size_t)m * 1024 + n0 + (tx << 2)] = r;
    }
}

// ---------------------------------------------------------------------------
// Kernel 3: per (b, i): top-16 + softmax + attn@V per head, head-avg + top-16
// for the A mask. One block (256 thr, 8 warps) per (b, i); warp w = head w.
// ---------------------------------------------------------------------------
__device__ __forceinline__ unsigned fkey(float f) {
    unsigned u = __float_as_uint(f);
    return (u & 0x80000000u) ? ~u : (u | 0x80000000u);
}

__global__ void __launch_bounds__(256) attn_kernel(float* __restrict__ dout)
{
    __shared__ float s_rows[8][1024];
    __shared__ float s_avg[1024];
    __shared__ int   s_selj[8][16];
    __shared__ float s_sela[8][16];

    int t  = threadIdx.x;
    int bi = blockIdx.x;                  // 0..16383
    int b  = bi >> 10, i = bi & 1023;

    for (int idx = t; idx < 8192; idx += 256) {
        int h = idx >> 10, j = idx & 1023;
        s_rows[h][j] = g_S[((size_t)((b << 3) + h) * 1024 + i) * 1024 + j];
    }
    __syncthreads();

    // head-average row + zero the A output row
    float* Arow = dout + 8388608 + (size_t)bi * 1024;
    for (int j = t; j < 1024; j += 256) {
        float s = 0.f;
#pragma unroll
        for (int h = 0; h < 8; h++) s += s_rows[h][j];
        s_avg[j] = s * 0.125f;
    }
    ((float4*)Arow)[t] = make_float4(0.f, 0.f, 0.f, 0.f);
    __syncthreads();

    int w = t >> 5, lane = t & 31;
    const float NEG = -1e30f;

    // ---- per-head: top-16 (iterative warp argmax), softmax, attn@V ----
    {
        float* row = s_rows[w];
        float myval = 0.f;
        int   myj   = 0;
        for (int it = 0; it < 16; it++) {
            float best = NEG; int bj = lane;
#pragma unroll
            for (int kk = 0; kk < 32; kk++) {
                float v = row[lane + (kk << 5)];
                if (v > best) { best = v; bj = lane + (kk << 5); }
            }
            // larger value wins; ties -> smaller index (matches jax top_k)
            unsigned long long key =
                ((unsigned long long)fkey(best) << 32) | (unsigned)(1023 - bj);
#pragma unroll
            for (int off = 16; off > 0; off >>= 1) {
                unsigned long long o = __shfl_xor_sync(0xFFFFFFFFu, key, off);
                if (o > key) key = o;
            }
            int jwin = 1023 - (int)(unsigned)(key & 0xFFFFFFFFull);
            if (lane == (jwin & 31)) row[jwin] = NEG;
            if (lane == it) {
                myj = jwin;
                unsigned hu = (unsigned)(key >> 32);
                myval = (hu & 0x80000000u) ? __uint_as_float(hu & 0x7FFFFFFFu)
                                           : __uint_as_float(~hu);
            }
            __syncwarp();
        }
        // softmax over the 16 selected (lane 0 holds the max)
        float mx = __shfl_sync(0xFFFFFFFFu, myval, 0);
        float e  = (lane < 16) ? __expf(myval - mx) : 0.f;
        float ss = e;
#pragma unroll
        for (int off = 16; off > 0; off >>= 1)
            ss += __shfl_xor_sync(0xFFFFFFFFu, ss, off);
        float aw = e / ss;
        if (lane < 16) { s_selj[w][lane] = myj; s_sela[w][lane] = aw; }
        __syncwarp();

        const float* Vb = g_V + ((size_t)((b << 3) + w) << 16);
        float o0 = 0.f, o1 = 0.f;
#pragma unroll
        for (int it = 0; it < 16; it++) {
            int   j  = s_selj[w][it];
            float a2 = s_sela[w][it];
            const float* vr = Vb + ((size_t)j << 6);
            o0 += a2 * vr[lane];
            o1 += a2 * vr[lane + 32];
        }
        float* Orow = g_O + (size_t)bi * 512 + (w << 6);
        Orow[lane]      = o0;
        Orow[lane + 32] = o1;
    }
    __syncthreads();

    // ---- warp 0: top-16 of the head-averaged row -> A mask ----
    if (w == 0) {
        for (int it = 0; it < 16; it++) {
            float best = NEG; int bj = lane;
#pragma unroll
            for (int kk = 0; kk < 32; kk++) {
                float v = s_avg[lane + (kk << 5)];
                if (v > best) { best = v; bj = lane + (kk << 5); }
            }
            unsigned long long key =
                ((unsigned long long)fkey(best) << 32) | (unsigned)(1023 - bj);
#pragma unroll
            for (int off = 16; off > 0; off >>= 1) {
                unsigned long long o = __shfl_xor_sync(0xFFFFFFFFu, key, off);
                if (o > key) key = o;
            }
            int jwin = 1023 - (int)(unsigned)(key & 0xFFFFFFFFull);
            if (lane == (jwin & 31)) { s_avg[jwin] = NEG; Arow[jwin] = 1.0f; }
            __syncwarp();
        }
    }
}

// ---------------------------------------------------------------------------
// Kernel 4: delta = O @ Wo^T + bo;  M_tilde = M + gate*delta  -> dout[0:8.4M]
// ---------------------------------------------------------------------------
__global__ void __launch_bounds__(256) proj_kernel(
    const float* __restrict__ Mm, const float* __restrict__ Wo,
    const float* __restrict__ bo, const float* __restrict__ gate,
    float* __restrict__ dout)
{
    __shared__ float As[16][68];
    __shared__ float Bs[16][68];

    int t  = threadIdx.x;
    int m0 = blockIdx.x << 6;
    int n0 = blockIdx.y << 6;
    int tx = t & 15, ty = t >> 4;
    int lr = t >> 2, lk = (t & 3) << 2;

    float acc[4][4];
#pragma unroll
    for (int u = 0; u < 4; u++)
#pragma unroll
        for (int v = 0; v < 4; v++) acc[u][v] = 0.f;

    const float* Ap = g_O + (size_t)(m0 + lr) * 512 + lk;
    const float* Bp = Wo  + (size_t)(n0 + lr) * 512 + lk;

    for (int k0 = 0; k0 < 512; k0 += 16) {
        float4 av = *(const float4*)(Ap + k0);
        float4 bv = *(const float4*)(Bp + k0);
        As[lk + 0][lr] = av.x; As[lk + 1][lr] = av.y;
        As[lk + 2][lr] = av.z; As[lk + 3][lr] = av.w;
        Bs[lk + 0][lr] = bv.x; Bs[lk + 1][lr] = bv.y;
        Bs[lk + 2][lr] = bv.z; Bs[lk + 3][lr] = bv.w;
        __syncthreads();
#pragma unroll
        for (int k = 0; k < 16; k++) {
            float4 a = *(const float4*)&As[k][ty << 2];
            float4 b = *(const float4*)&Bs[k][tx << 2];
            float a4[4] = {a.x, a.y, a.z, a.w};
            float b4[4] = {b.x, b.y, b.z, b.w};
#pragma unroll
            for (int u = 0; u < 4; u++)
#pragma unroll
                for (int v = 0; v < 4; v++) acc[u][v] += a4[u] * b4[v];
        }
        __syncthreads();
    }

    float g = gate[0];
    int n = n0 + (tx << 2);
    float4 bv4 = *(const float4*)&bo[n];
#pragma unroll
    for (int u = 0; u < 4; u++) {
        int m = m0 + (ty << 2) + u;
        float4 mv = *(const float4*)&Mm[(size_t)m * 512 + n];
        float4 r;
        r.x = mv.x + g * (acc[u][0] + bv4.x);
        r.y = mv.y + g * (acc[u][1] + bv4.y);
        r.z = mv.z + g * (acc[u][2] + bv4.z);
        r.w = mv.w + g * (acc[u][3] + bv4.w);
        *(float4*)&dout[(size_t)m * 512 + n] = r;
    }
}

// ---------------------------------------------------------------------------
extern "C" void kernel_launch(void* const* d_in, const int* in_sizes, int n_in,
                              void* d_out, int out_size)
{
    const float* Mm   = (const float*)d_in[0];
    const float* Wq   = (const float*)d_in[1];
    const float* Wk   = (const float*)d_in[2];
    const float* Wv   = (const float*)d_in[3];
    const float* Wo   = (const float*)d_in[4];
    const float* bo   = (const float*)d_in[5];
    const float* gate = (const float*)d_in[6];
    float* out = (float*)d_out;

    dim3 g1(16384 / 64, 512 / 64, 3);
    qkv_kernel<<<g1, 256>>>(Mm, Wq, Wk, Wv);

    dim3 g2(1024 / 64, 1024 / 64, 128);
    scores_kernel<<<g2, 256>>>();

    attn_kernel<<<16384, 256>>>(out);

    dim3 g4(16384 / 64, 512 / 64);
    proj_kernel<<<g4, 256>>>(Mm, Wo, bo, gate, out);
}

// round 5
// speedup vs baseline: 1.0230x; 1.0230x over previous
#include <cuda_runtime.h>

// ---------------------------------------------------------------------------
// CrossVariateAdapter: B=16, C=1024, NP=512, DM=512, H=8, D=64, TOPK=16
// Outputs concatenated: M_tilde (16*1024*512 fp32) then A (16*1024*1024 fp32)
// Round 5: f32x2 packed FMA (FFMA2) GEMMs, 128x128x8 tiles, 8x8 micro-tile.
// ---------------------------------------------------------------------------

// Scratch (static device memory — allocation-free per harness rules)
static __device__ float g_Q[8388608];      // (B*H, C, D)  33.5 MB
static __device__ float g_K[8388608];
static __device__ float g_V[8388608];
static __device__ float g_S[134217728];    // (B*H, C, C)  512 MB
static __device__ float g_O[8388608];      // (B*C, DM)    33.5 MB

// ---- f32x2 helpers --------------------------------------------------------
__device__ __forceinline__ unsigned long long pk2(float lo, float hi) {
    unsigned long long r;
    asm("mov.b64 %0, {%1, %2};" : "=l"(r) : "f"(lo), "f"(hi));
    return r;
}
__device__ __forceinline__ void fma2(unsigned long long& d,
                                     unsigned long long a,
                                     unsigned long long b) {
    asm("fma.rn.f32x2 %0, %1, %2, %0;" : "+l"(d) : "l"(a), "l"(b));
}
__device__ __forceinline__ float lo32(unsigned long long v) {
    return __uint_as_float((unsigned)v);
}
__device__ __forceinline__ float hi32(unsigned long long v) {
    return __uint_as_float((unsigned)(v >> 32));
}

// ---------------------------------------------------------------------------
// Kernel 1: QKV projections. q[m,n] = sum_k M[m,k] * W[n,k]
// BM=BN=128, BK=8, 256 threads, 8x8 micro-tile (f32x2 accumulators).
// Output laid out as (b, h, i, d).
// ---------------------------------------------------------------------------
__global__ void __launch_bounds__(256, 2) qkv_kernel(
    const float* __restrict__ Mm, const float* __restrict__ Wq,
    const float* __restrict__ Wk, const float* __restrict__ Wv)
{
    __shared__ float As[8][132];
    __shared__ float Bs[8][132];

    const float* W;
    float* out;
    if (blockIdx.z == 0)      { W = Wq; out = g_Q; }
    else if (blockIdx.z == 1) { W = Wk; out = g_K; }
    else                      { W = Wv; out = g_V; }

    int t  = threadIdx.x;
    int m0 = blockIdx.x << 7;     // over 16384
    int n0 = blockIdx.y << 7;     // over 512
    int tx = t & 15, ty = t >> 4;
    int lrow = t >> 1, lk4 = (t & 1) << 2;

    unsigned long long acc[8][4];
#pragma unroll
    for (int u = 0; u < 8; u++)
#pragma unroll
        for (int v = 0; v < 4; v++) acc[u][v] = 0ull;

    const float* Ap = Mm + (size_t)(m0 + lrow) * 512 + lk4;
    const float* Bp = W  + (size_t)(n0 + lrow) * 512 + lk4;

    for (int k0 = 0; k0 < 512; k0 += 8) {
        float4 av = *(const float4*)(Ap + k0);
        float4 bv = *(const float4*)(Bp + k0);
        As[lk4 + 0][lrow] = av.x; As[lk4 + 1][lrow] = av.y;
        As[lk4 + 2][lrow] = av.z; As[lk4 + 3][lrow] = av.w;
        Bs[lk4 + 0][lrow] = bv.x; Bs[lk4 + 1][lrow] = bv.y;
        Bs[lk4 + 2][lrow] = bv.z; Bs[lk4 + 3][lrow] = bv.w;
        __syncthreads();
#pragma unroll
        for (int k = 0; k < 8; k++) {
            float4 a0 = *(const float4*)&As[k][ty << 3];
            float4 a1 = *(const float4*)&As[k][(ty << 3) + 4];
            float4 b0 = *(const float4*)&Bs[k][tx << 3];
            float4 b1 = *(const float4*)&Bs[k][(tx << 3) + 4];
            unsigned long long bb0 = pk2(b0.x, b0.y), bb1 = pk2(b0.z, b0.w);
            unsigned long long bb2 = pk2(b1.x, b1.y), bb3 = pk2(b1.z, b1.w);
            float aa[8] = {a0.x, a0.y, a0.z, a0.w, a1.x, a1.y, a1.z, a1.w};
#pragma unroll
            for (int u = 0; u < 8; u++) {
                unsigned long long ad = pk2(aa[u], aa[u]);
                fma2(acc[u][0], ad, bb0);
                fma2(acc[u][1], ad, bb1);
                fma2(acc[u][2], ad, bb2);
                fma2(acc[u][3], ad, bb3);
            }
        }
        __syncthreads();
    }

    int nb = n0 + (tx << 3);
    int hh = nb >> 6, dd = nb & 63;      // 8-col run never crosses a head
#pragma unroll
    for (int u = 0; u < 8; u++) {
        int m  = m0 + (ty << 3) + u;
        int bb = m >> 10, ii = m & 1023;
        float* orow = out + (((size_t)(bb * 8 + hh) << 10) + ii) * 64 + dd;
        *(float4*)orow = make_float4(lo32(acc[u][0]), hi32(acc[u][0]),
                                     lo32(acc[u][1]), hi32(acc[u][1]));
        *(float4*)(orow + 4) = make_float4(lo32(acc[u][2]), hi32(acc[u][2]),
                                           lo32(acc[u][3]), hi32(acc[u][3]));
    }
}

// ---------------------------------------------------------------------------
// Kernel 2: batched scores S[z] = (Q[z] @ K[z]^T) * D^-0.5, z = b*H + h
// M=N=1024, K=64.  Same 128x128x8 / 8x8 f32x2 scheme.
// ---------------------------------------------------------------------------
__global__ void __launch_bounds__(256, 2) scores_kernel()
{
    __shared__ float As[8][132];
    __shared__ float Bs[8][132];

    int z = blockIdx.z;                       // 0..127
    const float* Q = g_Q + ((size_t)z << 16); // *1024*64
    const float* K = g_K + ((size_t)z << 16);
    float*       S = g_S + ((size_t)z << 20); // *1024*1024

    int t  = threadIdx.x;
    int m0 = blockIdx.x << 7;
    int n0 = blockIdx.y << 7;
    int tx = t & 15, ty = t >> 4;
    int lrow = t >> 1, lk4 = (t & 1) << 2;

    unsigned long long acc[8][4];
#pragma unroll
    for (int u = 0; u < 8; u++)
#pragma unroll
        for (int v = 0; v < 4; v++) acc[u][v] = 0ull;

    const float* Ap = Q + (size_t)(m0 + lrow) * 64 + lk4;
    const float* Bp = K + (size_t)(n0 + lrow) * 64 + lk4;

    for (int k0 = 0; k0 < 64; k0 += 8) {
        float4 av = *(const float4*)(Ap + k0);
        float4 bv = *(const float4*)(Bp + k0);
        As[lk4 + 0][lrow] = av.x; As[lk4 + 1][lrow] = av.y;
        As[lk4 + 2][lrow] = av.z; As[lk4 + 3][lrow] = av.w;
        Bs[lk4 + 0][lrow] = bv.x; Bs[lk4 + 1][lrow] = bv.y;
        Bs[lk4 + 2][lrow] = bv.z; Bs[lk4 + 3][lrow] = bv.w;
        __syncthreads();
#pragma unroll
        for (int k = 0; k < 8; k++) {
            float4 a0 = *(const float4*)&As[k][ty << 3];
            float4 a1 = *(const float4*)&As[k][(ty << 3) + 4];
            float4 b0 = *(const float4*)&Bs[k][tx << 3];
            float4 b1 = *(const float4*)&Bs[k][(tx << 3) + 4];
            unsigned long long bb0 = pk2(b0.x, b0.y), bb1 = pk2(b0.z, b0.w);
            unsigned long long bb2 = pk2(b1.x, b1.y), bb3 = pk2(b1.z, b1.w);
            float aa[8] = {a0.x, a0.y, a0.z, a0.w, a1.x, a1.y, a1.z, a1.w};
#pragma unroll
            for (int u = 0; u < 8; u++) {
                unsigned long long ad = pk2(aa[u], aa[u]);
                fma2(acc[u][0], ad, bb0);
                fma2(acc[u][1], ad, bb1);
                fma2(acc[u][2], ad, bb2);
                fma2(acc[u][3], ad, bb3);
            }
        }
        __syncthreads();
    }

    const float scale = 0.125f;   // 64^-0.5
    int nb = n0 + (tx << 3);
#pragma unroll
    for (int u = 0; u < 8; u++) {
        int m = m0 + (ty << 3) + u;
        float* srow = S + (size_t)m * 1024 + nb;
        *(float4*)srow = make_float4(lo32(acc[u][0]) * scale, hi32(acc[u][0]) * scale,
                                     lo32(acc[u][1]) * scale, hi32(acc[u][1]) * scale);
        *(float4*)(srow + 4) = make_float4(lo32(acc[u][2]) * scale, hi32(acc[u][2]) * scale,
                                           lo32(acc[u][3]) * scale, hi32(acc[u][3]) * scale);
    }
}

// ---------------------------------------------------------------------------
// Kernel 3: per (b, i): top-16 + softmax + attn@V per head, head-avg + top-16
// for the A mask. One block (256 thr, 8 warps) per (b, i); warp w = head w.
// ---------------------------------------------------------------------------
__device__ __forceinline__ unsigned fkey(float f) {
    unsigned u = __float_as_uint(f);
    return (u & 0x80000000u) ? ~u : (u | 0x80000000u);
}

__global__ void __launch_bounds__(256) attn_kernel(float* __restrict__ dout)
{
    __shared__ float s_rows[8][1024];
    __shared__ float s_avg[1024];
    __shared__ int   s_selj[8][16];
    __shared__ float s_sela[8][16];

    int t  = threadIdx.x;
    int bi = blockIdx.x;                  // 0..16383
    int b  = bi >> 10, i = bi & 1023;

    for (int idx = t; idx < 8192; idx += 256) {
        int h = idx >> 10, j = idx & 1023;
        s_rows[h][j] = g_S[((size_t)((b << 3) + h) * 1024 + i) * 1024 + j];
    }
    __syncthreads();

    // head-average row + zero the A output row
    float* Arow = dout + 8388608 + (size_t)bi * 1024;
    for (int j = t; j < 1024; j += 256) {
        float s = 0.f;
#pragma unroll
        for (int h = 0; h < 8; h++) s += s_rows[h][j];
        s_avg[j] = s * 0.125f;
    }
    ((float4*)Arow)[t] = make_float4(0.f, 0.f, 0.f, 0.f);
    __syncthreads();

    int w = t >> 5, lane = t & 31;
    const float NEG = -1e30f;

    // ---- per-head: top-16 (iterative warp argmax), softmax, attn@V ----
    {
        float* row = s_rows[w];
        float myval = 0.f;
        int   myj   = 0;
        for (int it = 0; it < 16; it++) {
            float best = NEG; int bj = lane;
#pragma unroll
            for (int kk = 0; kk < 32; kk++) {
                float v = row[lane + (kk << 5)];
                if (v > best) { best = v; bj = lane + (kk << 5); }
            }
            // larger value wins; ties -> smaller index (matches jax top_k)
            unsigned long long key =
                ((unsigned long long)fkey(best) << 32) | (unsigned)(1023 - bj);
#pragma unroll
            for (int off = 16; off > 0; off >>= 1) {
                unsigned long long o = __shfl_xor_sync(0xFFFFFFFFu, key, off);
                if (o > key) key = o;
            }
            int jwin = 1023 - (int)(unsigned)(key & 0xFFFFFFFFull);
            if (lane == (jwin & 31)) row[jwin] = NEG;
            if (lane == it) {
                myj = jwin;
                unsigned hu = (unsigned)(key >> 32);
                myval = (hu & 0x80000000u) ? __uint_as_float(hu & 0x7FFFFFFFu)
                                           : __uint_as_float(~hu);
            }
            __syncwarp();
        }
        // softmax over the 16 selected (lane 0 holds the max)
        float mx = __shfl_sync(0xFFFFFFFFu, myval, 0);
        float e  = (lane < 16) ? __expf(myval - mx) : 0.f;
        float ss = e;
#pragma unroll
        for (int off = 16; off > 0; off >>= 1)
            ss += __shfl_xor_sync(0xFFFFFFFFu, ss, off);
        float aw = e / ss;
        if (lane < 16) { s_selj[w][lane] = myj; s_sela[w][lane] = aw; }
        __syncwarp();

        const float* Vb = g_V + ((size_t)((b << 3) + w) << 16);
        float o0 = 0.f, o1 = 0.f;
#pragma unroll
        for (int it = 0; it < 16; it++) {
            int   j  = s_selj[w][it];
            float a2 = s_sela[w][it];
            const float* vr = Vb + ((size_t)j << 6);
            o0 += a2 * vr[lane];
            o1 += a2 * vr[lane + 32];
        }
        float* Orow = g_O + (size_t)bi * 512 + (w << 6);
        Orow[lane]      = o0;
        Orow[lane + 32] = o1;
    }
    __syncthreads();

    // ---- warp 0: top-16 of the head-averaged row -> A mask ----
    if (w == 0) {
        for (int it = 0; it < 16; it++) {
            float best = NEG; int bj = lane;
#pragma unroll
            for (int kk = 0; kk < 32; kk++) {
                float v = s_avg[lane + (kk << 5)];
                if (v > best) { best = v; bj = lane + (kk << 5); }
            }
            unsigned long long key =
                ((unsigned long long)fkey(best) << 32) | (unsigned)(1023 - bj);
#pragma unroll
            for (int off = 16; off > 0; off >>= 1) {
                unsigned long long o = __shfl_xor_sync(0xFFFFFFFFu, key, off);
                if (o > key) key = o;
            }
            int jwin = 1023 - (int)(unsigned)(key & 0xFFFFFFFFull);
            if (lane == (jwin & 31)) { s_avg[jwin] = NEG; Arow[jwin] = 1.0f; }
            __syncwarp();
        }
    }
}

// ---------------------------------------------------------------------------
// Kernel 4: delta = O @ Wo^T + bo;  M_tilde = M + gate*delta  -> dout[0:8.4M]
// ---------------------------------------------------------------------------
__global__ void __launch_bounds__(256, 2) proj_kernel(
    const float* __restrict__ Mm, const float* __restrict__ Wo,
    const float* __restrict__ bo, const float* __restrict__ gate,
    float* __restrict__ dout)
{
    __shared__ float As[8][132];
    __shared__ float Bs[8][132];

    int t  = threadIdx.x;
    int m0 = blockIdx.x << 7;
    int n0 = blockIdx.y << 7;
    int tx = t & 15, ty = t >> 4;
    int lrow = t >> 1, lk4 = (t & 1) << 2;

    unsigned long long acc[8][4];
#pragma unroll
    for (int u = 0; u < 8; u++)
#pragma unroll
        for (int v = 0; v < 4; v++) acc[u][v] = 0ull;

    const float* Ap = g_O + (size_t)(m0 + lrow) * 512 + lk4;
    const float* Bp = Wo  + (size_t)(n0 + lrow) * 512 + lk4;

    for (int k0 = 0; k0 < 512; k0 += 8) {
        float4 av = *(const float4*)(Ap + k0);
        float4 bv = *(const float4*)(Bp + k0);
        As[lk4 + 0][lrow] = av.x; As[lk4 + 1][lrow] = av.y;
        As[lk4 + 2][lrow] = av.z; As[lk4 + 3][lrow] = av.w;
        Bs[lk4 + 0][lrow] = bv.x; Bs[lk4 + 1][lrow] = bv.y;
        Bs[lk4 + 2][lrow] = bv.z; Bs[lk4 + 3][lrow] = bv.w;
        __syncthreads();
#pragma unroll
        for (int k = 0; k < 8; k++) {
            float4 a0 = *(const float4*)&As[k][ty << 3];
            float4 a1 = *(const float4*)&As[k][(ty << 3) + 4];
            float4 b0 = *(const float4*)&Bs[k][tx << 3];
            float4 b1 = *(const float4*)&Bs[k][(tx << 3) + 4];
            unsigned long long bb0 = pk2(b0.x, b0.y), bb1 = pk2(b0.z, b0.w);
            unsigned long long bb2 = pk2(b1.x, b1.y), bb3 = pk2(b1.z, b1.w);
            float aa[8] = {a0.x, a0.y, a0.z, a0.w, a1.x, a1.y, a1.z, a1.w};
#pragma unroll
            for (int u = 0; u < 8; u++) {
                unsigned long long ad = pk2(aa[u], aa[u]);
                fma2(acc[u][0], ad, bb0);
                fma2(acc[u][1], ad, bb1);
                fma2(acc[u][2], ad, bb2);
                fma2(acc[u][3], ad, bb3);
            }
        }
        __syncthreads();
    }

    float g = gate[0];
    int nb = n0 + (tx << 3);
    float4 bo0 = *(const float4*)&bo[nb];
    float4 bo1 = *(const float4*)&bo[nb + 4];
#pragma unroll
    for (int u = 0; u < 8; u++) {
        int m = m0 + (ty << 3) + u;
        const float* mrow = Mm + (size_t)m * 512 + nb;
        float4 m0v = *(const float4*)mrow;
        float4 m1v = *(const float4*)(mrow + 4);
        float4 r0, r1;
        r0.x = m0v.x + g * (lo32(acc[u][0]) + bo0.x);
        r0.y = m0v.y + g * (hi32(acc[u][0]) + bo0.y);
        r0.z = m0v.z + g * (lo32(acc[u][1]) + bo0.z);
        r0.w = m0v.w + g * (hi32(acc[u][1]) + bo0.w);
        r1.x = m1v.x + g * (lo32(acc[u][2]) + bo1.x);
        r1.y = m1v.y + g * (hi32(acc[u][2]) + bo1.y);
        r1.z = m1v.z + g * (lo32(acc[u][3]) + bo1.z);
        r1.w = m1v.w + g * (hi32(acc[u][3]) + bo1.w);
        float* drow = dout + (size_t)m * 512 + nb;
        *(float4*)drow = r0;
        *(float4*)(drow + 4) = r1;
    }
}

// ---------------------------------------------------------------------------
extern "C" void kernel_launch(void* const* d_in, const int* in_sizes, int n_in,
                              void* d_out, int out_size)
{
    const float* Mm   = (const float*)d_in[0];
    const float* Wq   = (const float*)d_in[1];
    const float* Wk   = (const float*)d_in[2];
    const float* Wv   = (const float*)d_in[3];
    const float* Wo   = (const float*)d_in[4];
    const float* bo   = (const float*)d_in[5];
    const float* gate = (const float*)d_in[6];
    float* out = (float*)d_out;

    dim3 g1(16384 / 128, 512 / 128, 3);
    qkv_kernel<<<g1, 256>>>(Mm, Wq, Wk, Wv);

    dim3 g2(1024 / 128, 1024 / 128, 128);
    scores_kernel<<<g2, 256>>>();

    attn_kernel<<<16384, 256>>>(out);

    dim3 g4(16384 / 128, 512 / 128);
    proj_kernel<<<g4, 256>>>(Mm, Wo, bo, gate, out);
}